// round 4
// baseline (speedup 1.0000x reference)
#include <cuda_runtime.h>
#include <math.h>

#define B_  16
#define L_  4096
#define D_  512
#define LP1 (L_ + 1)

// b = 100^(-1/256) = exp(-ln(100)/256), correctly rounded double.
#define POW_BASE 0.9821718891880367

// sin of the f32 angle l*fp (angle formed in f32 exactly like the reference),
// with double-precision Cody-Waite reduction so correctness is independent of
// --use_fast_math (naked sinf would become __sinf and blow up at |x| ~ 1e4).
__device__ __forceinline__ float emb_sin(float lf, float fp) {
    float x = __fmul_rn(lf, fp);                 // matches ref's f32 product
    double xd = (double)x;
    double k  = rint(xd * 0.15915494309189533576888376337251);  // 1/(2*pi)
    double r  = fma(-k, 6.283185307179586476925286766559, xd);  // |r| <= pi
    return sinf((float)r);                        // small-arg: cheap & exact
}

__global__ __launch_bounds__(512, 4)
void pe_kernel(const float* __restrict__ tokens,
               const int*   __restrict__ lengths,
               const float* __restrict__ cls,
               float*       __restrict__ out) {
    // blockDim = (128, 4): 4 rows per block, 128 threads x float4 cover D=512.
    // blockIdx.y in {0,1}: which half of the batch this block handles.
    __shared__ int s_len[B_];

    int d4 = threadIdx.x;                 // float4 index within the row
    int dd = d4 * 4;
    int lin = threadIdx.y * 128 + threadIdx.x;

    if (lin < B_) s_len[lin] = lengths[lin];
    __syncthreads();

    int row = blockIdx.x * 4 + threadIdx.y;
    if (row > L_) return;                 // after the only __syncthreads

    int b0 = blockIdx.y * (B_ / 2);       // 8 batches per thread

    const float* tok_row = tokens + (size_t)row * D_ + dd;
    float*       out_row = out    + (size_t)row * D_ + dd;

    // Per-thread freqs via pow-by-squaring in double (no exp, no smem table):
    //   f0 = b^(2*d4), f1 = b^(2*d4+1),  b = 100^(-1/256)
    double p  = 1.0;
    double bs = POW_BASE * POW_BASE;      // b^2
    int k = d4;                            // 7 bits
#pragma unroll
    for (int i = 0; i < 7; i++) {
        if (k & 1) p *= bs;
        bs *= bs;
        k >>= 1;
    }
    const float PI2F = 1.57079637050628662109375f;  // float(pi/2)
    float f0 = (float)p;
    float f1 = (float)(p * POW_BASE);

    // Positional embedding for this (row, dd..dd+3) — reused across the
    // 8 batch elements this thread owns. Row L has no embedding.
    float4 emb = make_float4(0.f, 0.f, 0.f, 0.f);
    if (row < L_) {
        float lf = (float)row;
        emb.x = emb_sin(lf, f0);
        emb.y = emb_sin(lf, f0 + PI2F);
        emb.z = emb_sin(lf, f1);
        emb.w = emb_sin(lf, f1 + PI2F);
    }

    float4 cls4 = *reinterpret_cast<const float4*>(cls + dd);

    // Simple per-batch loop (R1 style): low register pressure, MLP comes
    // from 100% occupancy (2048 threads/SM), not from in-thread staging.
#pragma unroll
    for (int j = 0; j < B_ / 2; j++) {
        int b   = b0 + j;
        int len = s_len[b];
        float4 o;
        if (row < len) {
            float4 t = __ldcs(reinterpret_cast<const float4*>(
                          tok_row + (size_t)b * ((size_t)L_ * D_)));
            o = make_float4(t.x + emb.x, t.y + emb.y,
                            t.z + emb.z, t.w + emb.w);
        } else if (row == len) {
            o = cls4;                     // x was zeroed here, so out = cls
        } else {
            o = make_float4(0.f, 0.f, 0.f, 0.f);
        }
        __stcs(reinterpret_cast<float4*>(
                   out_row + (size_t)b * ((size_t)LP1 * D_)), o);
    }
}

extern "C" void kernel_launch(void* const* d_in, const int* in_sizes, int n_in,
                              void* d_out, int out_size) {
    const float* tokens  = (const float*)d_in[0];  // [B, L, D] f32
    const int*   lengths = (const int*)  d_in[1];  // [B] i32
    const float* cls     = (const float*)d_in[2];  // [D] f32
    float*       out     = (float*)d_out;          // [B, L+1, D] f32

    (void)in_sizes; (void)n_in; (void)out_size;

    dim3 blk(128, 4);
    dim3 grid((LP1 + 3) / 4, 2);          // 1025 x 2 blocks, rows 0..4096
    pe_kernel<<<grid, blk>>>(tokens, lengths, cls, out);
}

// round 5
// speedup vs baseline: 1.5015x; 1.5015x over previous
#include <cuda_runtime.h>
#include <math.h>

#define B_  16
#define L_  4096
#define D_  512
#define LP1 (L_ + 1)

// Per-d angular rate: fp[d] = float(100^{-(d - d%2)/D}) + float(pi/2)*(d%2)
// Filled by a 2KB graph memcpy node from a host-computed table (double pow,
// identical values to the reference).
__device__ float g_fp[D_];

// sin of the f32 angle l*fp (angle formed in f32 exactly like the reference),
// with double-precision Cody-Waite reduction so correctness is independent of
// --use_fast_math (naked sinf would become __sinf and blow up at |x| ~ 1e4).
__device__ __forceinline__ float emb_sin(float lf, float fp) {
    float x = __fmul_rn(lf, fp);                 // matches ref's f32 product
    double xd = (double)x;
    double k  = rint(xd * 0.15915494309189533576888376337251);  // 1/(2*pi)
    double r  = fma(-k, 6.283185307179586476925286766559, xd);  // |r| <= pi
    return sinf((float)r);                        // small-arg: cheap & exact
}

// ===== EXACT R1 kernel body (fastest measured: 32.4us, regs=32, occ=81%) ====
__global__ __launch_bounds__(512)
void pe_kernel(const float* __restrict__ tokens,
               const int*   __restrict__ lengths,
               const float* __restrict__ cls,
               float*       __restrict__ out) {
    // One row per warp-group-of-4-warps: 128 threads cover D=512 via float4.
    // blockDim = (128, 4) -> 4 rows per block. Rows 0..L inclusive (L+1 rows).
    int row = blockIdx.x * 4 + threadIdx.y;
    if (row > L_) return;

    int d4 = threadIdx.x;                 // float4 index within the row
    int dd = d4 * 4;

    float4 fp   = *reinterpret_cast<const float4*>(g_fp + dd);
    float4 cls4 = *reinterpret_cast<const float4*>(cls  + dd);

    // Positional embedding for this (row, d..d+3) — computed ONCE, reused
    // across all 16 batch elements. Row L has no embedding.
    float4 emb = make_float4(0.f, 0.f, 0.f, 0.f);
    if (row < L_) {
        float lf = (float)row;
        emb.x = emb_sin(lf, fp.x);
        emb.y = emb_sin(lf, fp.y);
        emb.z = emb_sin(lf, fp.z);
        emb.w = emb_sin(lf, fp.w);
    }

    int lens[B_];
#pragma unroll
    for (int b = 0; b < B_; b++) lens[b] = __ldg(lengths + b);

#pragma unroll
    for (int b = 0; b < B_; b++) {
        float4 o;
        if (row < lens[b]) {
            // valid token: tokens + emb
            const float4 t = *reinterpret_cast<const float4*>(
                tokens + ((size_t)b * L_ + row) * D_ + dd);
            o = make_float4(t.x + emb.x, t.y + emb.y, t.z + emb.z, t.w + emb.w);
        } else if (row == lens[b]) {
            // CLS row (x was zeroed here in the reference, so out = cls)
            o = cls4;
        } else {
            o = make_float4(0.f, 0.f, 0.f, 0.f);
        }
        *reinterpret_cast<float4*>(
            out + ((size_t)b * LP1 + row) * D_ + dd) = o;
    }
}

// Persistent host-side table: must outlive graph replays (memcpy node reads it).
static float h_fp[D_];

extern "C" void kernel_launch(void* const* d_in, const int* in_sizes, int n_in,
                              void* d_out, int out_size) {
    const float* tokens  = (const float*)d_in[0];  // [B, L, D] f32
    const int*   lengths = (const int*)  d_in[1];  // [B] i32
    const float* cls     = (const float*)d_in[2];  // [D] f32
    float*       out     = (float*)d_out;          // [B, L+1, D] f32

    (void)in_sizes; (void)n_in; (void)out_size;

    // Host-side fp table (deterministic, same math as reference):
    // freq = f32(100^{-(d - d%2)/D}), phase = f32(pi/2)*(d%2), fp = freq+phase.
    const float PI2F = 1.57079637050628662109375f;  // float(pi/2)
    for (int d = 0; d < D_; d++) {
        double t = (double)(d & ~1) / (double)D_;
        float freq = (float)pow(100.0, -t);
        h_fp[d] = (d & 1) ? (freq + PI2F) : freq;
    }
    // 2KB H2D memcpy node (graph-capturable, replayed from persistent h_fp).
    cudaMemcpyToSymbolAsync(g_fp, h_fp, sizeof(h_fp), 0,
                            cudaMemcpyHostToDevice, 0);

    dim3 blk(128, 4);
    int grid = (LP1 + 3) / 4;                      // 1025 blocks, rows 0..4096
    pe_kernel<<<grid, blk>>>(tokens, lengths, cls, out);
}